// round 16
// baseline (speedup 1.0000x reference)
#include <cuda_runtime.h>
#include <cuda_bf16.h>
#include <stdint.h>
#include <math.h>

// Shapes: B=4, S=512, V=32000, E=256, H=512/dir, D=1024, NH=8, dk=128, NLAYERS=6
// M = B*S = 2048 everywhere.

__device__ float         g_xe[2048 * 256];
__device__ float         g_pre[2 * 2048 * 2048];
__device__ float         g_ha[2048 * 1024];
__device__ float         g_hb[2048 * 1024];
__device__ float         g_qkv[2048 * 3072];
__device__ float         g_sc[32 * 512 * 512];
__device__ float         g_ao[2048 * 1024];
__device__ float         g_att[2048 * 1024];
__device__ float         g_ff[2048 * 4096];
__device__ float         g_hstate[2 * 2 * 4 * 512];
__device__ unsigned      g_ctr;
__device__ __nv_bfloat16 g_wh[32000 * 1024];
__device__ __nv_bfloat16 g_wl[32000 * 1024];
__device__ __nv_bfloat16 g_xh[2048 * 4096];
__device__ __nv_bfloat16 g_xl[2048 * 4096];

__device__ __forceinline__ unsigned smem_u32(const void* p) {
    unsigned a;
    asm("{ .reg .u64 t; cvta.to.shared.u64 t, %1; cvt.u32.u64 %0, t; }" : "=r"(a) : "l"(p));
    return a;
}
#define CPA16(sa, g) \
    asm volatile("cp.async.cg.shared.global [%0], [%1], 16;" :: "r"(sa), "l"(g) : "memory")
#define CPA_COMMIT() asm volatile("cp.async.commit_group;" ::: "memory")
#define CPA_WAIT1()  asm volatile("cp.async.wait_group 1;" ::: "memory")

#define LDSM4(r0, r1, r2, r3, addr) \
    asm volatile("ldmatrix.sync.aligned.m8n8.x4.shared.b16 {%0,%1,%2,%3}, [%4];" \
                 : "=r"(r0), "=r"(r1), "=r"(r2), "=r"(r3) : "r"(addr))

#define MMA16(d, a, b0, b1) \
    asm volatile("mma.sync.aligned.m16n8k16.row.col.f32.bf16.bf16.f32 " \
                 "{%0,%1,%2,%3},{%4,%5,%6,%7},{%8,%9},{%0,%1,%2,%3};" \
                 : "+f"((d)[0]), "+f"((d)[1]), "+f"((d)[2]), "+f"((d)[3]) \
                 : "r"((a)[0]), "r"((a)[1]), "r"((a)[2]), "r"((a)[3]), "r"(b0), "r"(b1))

__global__ __launch_bounds__(256) void cvt_split(const float* __restrict__ X,
                                                 __nv_bfloat16* __restrict__ H,
                                                 __nv_bfloat16* __restrict__ L,
                                                 int n4)
{
    const int i = blockIdx.x * 256 + threadIdx.x;
    if (i >= n4) return;
    const float4 v = ((const float4*)X)[i];
    __nv_bfloat16 hx = __float2bfloat16_rn(v.x);
    __nv_bfloat16 hy = __float2bfloat16_rn(v.y);
    __nv_bfloat16 hz = __float2bfloat16_rn(v.z);
    __nv_bfloat16 hw = __float2bfloat16_rn(v.w);
    __nv_bfloat16 lx = __float2bfloat16_rn(v.x - __bfloat162float(hx));
    __nv_bfloat16 ly = __float2bfloat16_rn(v.y - __bfloat162float(hy));
    __nv_bfloat16 lz = __float2bfloat16_rn(v.z - __bfloat162float(hz));
    __nv_bfloat16 lw = __float2bfloat16_rn(v.w - __bfloat162float(hw));
    __nv_bfloat162* H2 = (__nv_bfloat162*)H;
    __nv_bfloat162* L2 = (__nv_bfloat162*)L;
    H2[i * 2]     = __nv_bfloat162(hx, hy);
    H2[i * 2 + 1] = __nv_bfloat162(hz, hw);
    L2[i * 2]     = __nv_bfloat162(lx, ly);
    L2[i * 2 + 1] = __nv_bfloat162(lz, lw);
}

#define TPITCH 144
#define TMAT   (128 * TPITCH)
#define TSTAGE (4 * TMAT)
#define TG_SMEM (2 * TSTAGE)

__device__ __forceinline__ void tg_issue(char* sbase,
                                         const __nv_bfloat16* __restrict__ Ah,
                                         const __nv_bfloat16* __restrict__ Al,
                                         const __nv_bfloat16* __restrict__ Wh,
                                         const __nv_bfloat16* __restrict__ Wl,
                                         int bm, int bn, int K, int k0, int tid)
{
#pragma unroll
    for (int i = 0; i < 16; i++) {
        const int s   = tid + (i << 8);
        const int mat = s >> 10;
        const int r   = (s >> 3) & 127;
        const int cs  = s & 7;
        const __nv_bfloat16* g;
        if (mat == 0)      g = Ah + (size_t)(bm + r) * K + k0 + cs * 8;
        else if (mat == 1) g = Al + (size_t)(bm + r) * K + k0 + cs * 8;
        else if (mat == 2) g = Wh + (size_t)(bn + r) * K + k0 + cs * 8;
        else               g = Wl + (size_t)(bn + r) * K + k0 + cs * 8;
        const unsigned sa = smem_u32(sbase + mat * TMAT + r * TPITCH + cs * 16);
        CPA16(sa, g);
    }
}

__global__ __launch_bounds__(256) void tgemm(const __nv_bfloat16* __restrict__ Ah,
                                             const __nv_bfloat16* __restrict__ Al,
                                             const __nv_bfloat16* __restrict__ Wh,
                                             const __nv_bfloat16* __restrict__ Wl,
                                             const float* __restrict__ bias,
                                             float* __restrict__ C,
                                             int M, int N, int K, int ldc, int relu)
{
    extern __shared__ __align__(128) char sm[];
    const int tid  = threadIdx.x;
    const int wid  = tid >> 5;
    const int lane = tid & 31;
    const int wm   = wid >> 2;
    const int wn   = wid & 3;
    const int bm   = blockIdx.y << 7;
    const int bn   = blockIdx.x << 7;
    const int nch  = K >> 6;

    tg_issue(sm,          Ah, Al, Wh, Wl, bm, bn, K, 0,  tid);
    CPA_COMMIT();
    tg_issue(sm + TSTAGE, Ah, Al, Wh, Wl, bm, bn, K, 64, tid);
    CPA_COMMIT();

    float acc[4][4][4];
#pragma unroll
    for (int a = 0; a < 4; a++)
#pragma unroll
        for (int b = 0; b < 4; b++)
#pragma unroll
            for (int c = 0; c < 4; c++) acc[a][b][c] = 0.f;

    for (int c = 0; c < nch; c++) {
        CPA_WAIT1();
        __syncthreads();
        char* sb = sm + (c & 1) * TSTAGE;
        const unsigned sA = smem_u32(sb);

#pragma unroll
        for (int k16 = 0; k16 < 4; k16++) {
            const unsigned kb   = (unsigned)(k16 * 32 + ((lane >> 4) << 4));
            const unsigned arow = (unsigned)(lane & 15);

            unsigned ah[4][4], al[4][4];
#pragma unroll
            for (int mt = 0; mt < 4; mt++) {
                const unsigned ra = sA + (wm * 64 + mt * 16 + arow) * TPITCH + kb;
                LDSM4(ah[mt][0], ah[mt][1], ah[mt][2], ah[mt][3], ra);
                LDSM4(al[mt][0], al[mt][1], al[mt][2], al[mt][3], ra + TMAT);
            }
#pragma unroll
            for (int np = 0; np < 2; np++) {
                const unsigned rb = sA + 2 * TMAT + (wn * 32 + np * 16 + arow) * TPITCH + kb;
                unsigned bh[4], bl[4];
                LDSM4(bh[0], bh[1], bh[2], bh[3], rb);
                LDSM4(bl[0], bl[1], bl[2], bl[3], rb + TMAT);
#pragma unroll
                for (int mt = 0; mt < 4; mt++) {
                    MMA16(acc[mt][np * 2],     ah[mt], bh[0], bh[2]);
                    MMA16(acc[mt][np * 2],     ah[mt], bl[0], bl[2]);
                    MMA16(acc[mt][np * 2],     al[mt], bh[0], bh[2]);
                    MMA16(acc[mt][np * 2 + 1], ah[mt], bh[1], bh[3]);
                    MMA16(acc[mt][np * 2 + 1], ah[mt], bl[1], bl[3]);
                    MMA16(acc[mt][np * 2 + 1], al[mt], bh[1], bh[3]);
                }
            }
        }
        __syncthreads();
        if (c + 2 < nch)
            tg_issue(sm + (c & 1) * TSTAGE, Ah, Al, Wh, Wl, bm, bn, K, (c + 2) * 64, tid);
        CPA_COMMIT();
    }

#pragma unroll
    for (int mt = 0; mt < 4; mt++) {
#pragma unroll
        for (int nt = 0; nt < 4; nt++) {
            const int r0 = bm + wm * 64 + mt * 16 + (lane >> 2);
            const int cl = bn + wn * 32 + nt * 8 + (lane & 3) * 2;
            const float b0v = bias[cl], b1v = bias[cl + 1];
            float v0 = acc[mt][nt][0] + b0v;
            float v1 = acc[mt][nt][1] + b1v;
            float v2 = acc[mt][nt][2] + b0v;
            float v3 = acc[mt][nt][3] + b1v;
            if (relu) {
                v0 = fmaxf(v0, 0.f); v1 = fmaxf(v1, 0.f);
                v2 = fmaxf(v2, 0.f); v3 = fmaxf(v3, 0.f);
            }
            C[(size_t)r0 * ldc + cl]           = v0;
            C[(size_t)r0 * ldc + cl + 1]       = v1;
            C[(size_t)(r0 + 8) * ldc + cl]     = v2;
            C[(size_t)(r0 + 8) * ldc + cl + 1] = v3;
        }
    }
}

__global__ void embed_kernel(const int* __restrict__ x,
                             const float* __restrict__ emb,
                             float* __restrict__ out)
{
    const int row = blockIdx.x;
    const int tid = threadIdx.x;
    const int idx = x[row];
    out[(size_t)row * 256 + tid] = emb[(size_t)idx * 256 + tid];
}

#define LS_WP 516
#define LS_SMEM ((64 * LS_WP + 4 * LS_WP + 256 + 64) * 4)

__global__ __launch_bounds__(256) void lstm_scan(const float* __restrict__ pre,
                                                 const float* __restrict__ Whh,
                                                 float* __restrict__ hstate,
                                                 float* __restrict__ out,
                                                 unsigned* __restrict__ ctr)
{
    extern __shared__ float ls_sm[];
    float* wsm = ls_sm;
    float* hsm = ls_sm + 64 * LS_WP;
    float* gsm = hsm + 4 * LS_WP;
    float* csm = gsm + 256;

    const int tid  = threadIdx.x;
    const int dir  = blockIdx.x >> 5;
    const int base = (blockIdx.x & 31) << 4;
    const int gu   = tid >> 2;
    const int b    = tid & 3;
    const int grow = ((gu >> 4) << 9) + base + (gu & 15);

    const float* Wd   = Whh + (size_t)dir * 2048 * 512;
    const float* pred = pre + (size_t)dir * 2048 * 2048;

    for (int i = tid; i < 64 * 128; i += 256) {
        const int row = i >> 7;
        const int c   = (i & 127) << 2;
        const float4 v = *(const float4*)&Wd[(size_t)(((row >> 4) << 9) + base + (row & 15)) * 512 + c];
        float* w = &wsm[row * LS_WP + c];
        w[0] = v.x; w[1] = v.y; w[2] = v.z; w[3] = v.w;
    }
    if (tid < 64) {
        csm[tid] = 0.f;
        const int uu = tid >> 2, bb = tid & 3;
        hstate[((dir * 2 + 0) * 4 + bb) * 512 + base + uu] = 0.f;
    }
    __threadfence();
    __syncthreads();

    unsigned want = gridDim.x;
    if (tid == 0) {
        atomicAdd(ctr, 1u);
        while (*(volatile unsigned*)ctr < want) __nanosleep(64);
        __threadfence();
    }
    __syncthreads();

    for (int t = 0; t < 512; t++) {
        const int s  = dir ? (511 - t) : t;
        const int rb = t & 1;

        const float* hg = hstate + (size_t)(dir * 2 + rb) * 4 * 512;
        for (int i = tid; i < 2048; i += 256)
            hsm[(i >> 9) * LS_WP + (i & 511)] = hg[i];
        __syncthreads();

        float acc = pred[(size_t)((b << 9) + s) * 2048 + grow];
        const float* wr = wsm + gu * LS_WP;
        const float* hr = hsm + b * LS_WP;
#pragma unroll 8
        for (int k = 0; k < 512; k += 4) {
            const float4 w = *(const float4*)(wr + k);
            const float4 h = *(const float4*)(hr + k);
            acc += w.x * h.x + w.y * h.y + w.z * h.z + w.w * h.w;
        }
        gsm[tid] = acc;
        __syncthreads();

        if (tid < 64) {
            const int uu = tid >> 2, bb = tid & 3;
            const float iv = 1.f / (1.f + expf(-gsm[tid]));
            const float fv = 1.f / (1.f + expf(-gsm[64 + tid]));
            const float gv = tanhf(gsm[128 + tid]);
            const float ov = 1.f / (1.f + expf(-gsm[192 + tid]));
            const float c  = fv * csm[tid] + iv * gv;
            csm[tid] = c;
            const float h = ov * tanhf(c);
            hstate[((dir * 2 + (rb ^ 1)) * 4 + bb) * 512 + base + uu] = h;
            out[(size_t)((bb << 9) + s) * 1024 + (dir << 9) + base + uu] = h;
            __threadfence();
        }
        __syncthreads();

        want += gridDim.x;
        if (tid == 0) {
            atomicAdd(ctr, 1u);
            while (*(volatile unsigned*)ctr < want) __nanosleep(64);
            __threadfence();
        }
        __syncthreads();
    }
}

__global__ void reset_ctr(unsigned* c) { *c = 0u; }

__global__ __launch_bounds__(256) void ln_kernel(const float* __restrict__ X,
                                                 const float* __restrict__ R,
                                                 const float* __restrict__ g,
                                                 const float* __restrict__ bta,
                                                 float* __restrict__ Y)
{
    __shared__ float red[16];
    const int row = blockIdx.x;
    const int tid = threadIdx.x;
    const size_t off = (size_t)row * 1024;

    float loc[4];
    float s = 0.f;
#pragma unroll
    for (int i = 0; i < 4; i++) {
        const int c = tid + i * 256;
        float v = X[off + c];
        if (R) v += R[off + c];
        loc[i] = v;
        s += v;
    }
#pragma unroll
    for (int o = 16; o; o >>= 1) s += __shfl_xor_sync(0xffffffffu, s, o);
    if ((tid & 31) == 0) red[tid >> 5] = s;
    __syncthreads();
    if (tid == 0) { float t = 0; for (int i = 0; i < 8; i++) t += red[i]; red[8] = t; }
    __syncthreads();
    const float mean = red[8] * (1.f / 1024.f);

    float s2 = 0.f;
#pragma unroll
    for (int i = 0; i < 4; i++) { const float d = loc[i] - mean; s2 += d * d; }
#pragma unroll
    for (int o = 16; o; o >>= 1) s2 += __shfl_xor_sync(0xffffffffu, s2, o);
    __syncthreads();
    if ((tid & 31) == 0) red[tid >> 5] = s2;
    __syncthreads();
    if (tid == 0) { float t = 0; for (int i = 0; i < 8; i++) t += red[i]; red[8] = t; }
    __syncthreads();
    const float inv = rsqrtf(red[8] * (1.f / 1024.f) + 1e-5f);

#pragma unroll
    for (int i = 0; i < 4; i++) {
        const int c = tid + i * 256;
        Y[off + c] = (loc[i] - mean) * inv * g[c] + bta[c];
    }
}

#define SC_SMEM (2 * 64 * 129 * 4)
__global__ __launch_bounds__(256) void attn_scores(const float* __restrict__ qkv,
                                                   float* __restrict__ sc)
{
    extern __shared__ float smq[];
    float* Qs = smq;
    float* Ks = smq + 64 * 129;

    const int bh = blockIdx.z;
    const int b  = bh >> 3, h = bh & 7;
    const int q0 = blockIdx.y << 6, k0 = blockIdx.x << 6;
    const int tid = threadIdx.x;

    const float* Qg = qkv + (size_t)(b * 512 + q0) * 3072 + h * 128;
    const float* Kg = qkv + (size_t)(b * 512 + k0) * 3072 + 1024 + h * 128;

    for (int i = tid; i < 64 * 128; i += 256) {
        const int r = i >> 7, c = i & 127;
        Qs[r * 129 + c] = Qg[(size_t)r * 3072 + c];
        Ks[r * 129 + c] = Kg[(size_t)r * 3072 + c];
    }
    __syncthreads();

    const int tx = tid & 15, ty = tid >> 4;
    float acc[4][4];
#pragma unroll
    for (int i = 0; i < 4; i++)
#pragma unroll
        for (int j = 0; j < 4; j++) acc[i][j] = 0.f;

    for (int kk = 0; kk < 128; kk++) {
        float ar[4], br[4];
#pragma unroll
        for (int i = 0; i < 4; i++) ar[i] = Qs[(ty * 4 + i) * 129 + kk];
#pragma unroll
        for (int j = 0; j < 4; j++) br[j] = Ks[(tx * 4 + j) * 129 + kk];
#pragma unroll
        for (int i = 0; i < 4; i++)
#pragma unroll
            for (int j = 0; j < 4; j++) acc[i][j] += ar[i] * br[j];
    }

    const float scale = 0.08838834764831845f;
    float* o = sc + ((size_t)bh * 512 + q0) * 512 + k0;
#pragma unroll
    for (int i = 0; i < 4; i++)
#pragma unroll
        for (int j = 0; j < 4; j++)
            o[(size_t)(ty * 4 + i) * 512 + tx * 4 + j] = acc[i][j] * scale;
}

__global__ __launch_bounds__(256) void attn_softmax(float* __restrict__ sc)
{
    const int row  = blockIdx.x * 8 + (threadIdx.x >> 5);
    const int lane = threadIdx.x & 31;
    float* p = sc + (size_t)row * 512;

    float v[16];
    float m = -1e30f;
#pragma unroll
    for (int i = 0; i < 16; i++) { v[i] = p[lane + i * 32]; m = fmaxf(m, v[i]); }
#pragma unroll
    for (int o = 16; o; o >>= 1) m = fmaxf(m, __shfl_xor_sync(0xffffffffu, m, o));
    float s = 0.f;
#pragma unroll
    for (int i = 0; i < 16; i++) { v[i] = expf(v[i] - m); s += v[i]; }
#pragma unroll
    for (int o = 16; o; o >>= 1) s += __shfl_xor_sync(0xffffffffu, s, o);
    const float r = 1.f / s;
#pragma unroll
    for (int i = 0; i < 16; i++) p[lane + i * 32] = v[i] * r;
}

#define PV_SMEM ((64 * 65 + 64 * 129) * 4)
__global__ __launch_bounds__(256) void attn_pv(const float* __restrict__ sc,
                                               const float* __restrict__ qkv,
                                               float* __restrict__ ao)
{
    extern __shared__ float smp[];
    float* Ws = smp;
    float* Vs = smp + 64 * 65;

    const int bh = blockIdx.y;
    const int b  = bh >> 3, h = bh & 7;
    const int q0 = blockIdx.x << 6;
    const int tid = threadIdx.x;
    const int tx = tid & 15, ty = tid >> 4;

    const float* scb = sc + ((size_t)bh * 512 + q0) * 512;
    const float* Vg  = qkv + (size_t)b * 512 * 3072 + 2048 + h * 128;

    float acc[4][8];
#pragma unroll
    for (int i = 0; i < 4; i++)
#pragma unroll
        for (int j = 0; j < 8; j++) acc[i][j] = 0.f;

    for (int kt = 0; kt < 512; kt += 64) {
        for (int i = tid; i < 64 * 64; i += 256) {
            const int r = i >> 6, c = i & 63;
            Ws[r * 65 + c] = scb[(size_t)r * 512 + kt + c];
        }
        for (int i = tid; i < 64 * 128; i += 256) {
            const int r = i >> 7, c = i & 127;
            Vs[r * 129 + c] = Vg[(size_t)(kt + r) * 3072 + c];
        }
        __syncthreads();
        for (int kk = 0; kk < 64; kk++) {
            float ar[4], br[8];
#pragma unroll
            for (int i = 0; i < 4; i++) ar[i] = Ws[(ty * 4 + i) * 65 + kk];
#pragma unroll
            for (int j = 0; j < 8; j++) br[j] = Vs[kk * 129 + tx * 8 + j];
#pragma unroll
            for (int i = 0; i < 4; i++)
#pragma unroll
                for (int j = 0; j < 8; j++) acc[i][j] += ar[i] * br[j];
        }
        __syncthreads();
    }

    float* og = ao + (size_t)(b * 512 + q0) * 1024 + h * 128;
#pragma unroll
    for (int i = 0; i < 4; i++)
#pragma unroll
        for (int j = 0; j < 8; j++)
            og[(size_t)(ty * 4 + i) * 1024 + tx * 8 + j] = acc[i][j];
}

static void run_gemm(const float* A, const float* W, const float* bias, float* C,
                     int M, int N, int K, int ldc, int relu,
                     __nv_bfloat16* xh, __nv_bfloat16* xl,
                     __nv_bfloat16* wh, __nv_bfloat16* wl)
{
    const int na4 = (M * K) / 4;
    const int nw4 = (N * K) / 4;
    cvt_split<<<(na4 + 255) / 256, 256>>>(A, xh, xl, na4);
    cvt_split<<<(nw4 + 255) / 256, 256>>>(W, wh, wl, nw4);
    tgemm<<<dim3(N / 128, M / 128), 256, TG_SMEM>>>(xh, xl, wh, wl, bias, C, M, N, K, ldc, relu);
}

extern "C" void kernel_launch(void* const* d_in, const int* in_sizes, int n_in,
                              void* d_out, int out_size)
{
    (void)in_sizes; (void)n_in; (void)out_size;

    const int*   x     = (const int*)  d_in[0];
    const float* emb   = (const float*)d_in[1];
    const float* Wih0  = (const float*)d_in[2];
    const float* Whh0  = (const float*)d_in[3];
    const float* b0    = (const float*)d_in[4];
    const float* Wih12 = (const float*)d_in[5];
    const float* Whh12 = (const float*)d_in[6];
    const float* b12   = (const float*)d_in[7];
    const float* ln_g  = (const float*)d_in[8];
    const float* ln_b  = (const float*)d_in[9];
    const float* Wqkv  = (const float*)d_in[10];
    const float* bqkv  = (const float*)d_in[11];
    const float* Wo    = (const float*)d_in[12];
    const float* bo    = (const float*)d_in[13];
    const float* ln1g  = (const float*)d_in[14];
    const float* ln1b  = (const float*)d_in[15];
    const float* W1    = (const float*)d_in[16];
    const float* b1    = (const float*)d_in[17];
    const float* W2    = (const float*)d_in[18];
    const float* b2    = (const float*)d_in[19];
    const float* ln2g  = (const float*)d_in[20];
    const float* ln2b  = (const float*)d_in[21];
    const float* attnW = (const float*)d_in[22];
    const float* attnb = (const float*)d_in[23];
    const float* outW  = (const float*)d_in[24];
    const float* outb  = (const float*)d_in[25];
    float* OUT = (float*)d_out;

    float *xe, *pre, *ha, *hb, *qkv, *sc, *ao, *att, *ff, *hstate;
    unsigned* ctr;
    __nv_bfloat16 *wh, *wl, *xh, *xl;
    cudaGetSymbolAddress((void**)&xe, g_xe);
    cudaGetSymbolAddress((void**)&pre, g_pre);
    cudaGetSymbolAddress((void**)&ha, g_ha);
    cudaGetSymbolAddress((void**)&hb, g_hb);
    cudaGetSymbolAddress((void**)&qkv, g_qkv);
    cudaGetSymbolAddress((void**)&sc, g_sc);
    cudaGetSymbolAddress((void**)&ao, g_ao);
    cudaGetSymbolAddress((void**)&att, g_att);
    cudaGetSymbolAddress((void**)&ff, g_ff);
    cudaGetSymbolAddress((void**)&hstate, g_hstate);
    cudaGetSymbolAddress((void**)&ctr, g_ctr);
    cudaGetSymbolAddress((void**)&wh, g_wh);
    cudaGetSymbolAddress((void**)&wl, g_wl);
    cudaGetSymbolAddress((void**)&xh, g_xh);
    cudaGetSymbolAddress((void**)&xl, g_xl);

    cudaFuncSetAttribute(tgemm,       cudaFuncAttributeMaxDynamicSharedMemorySize, TG_SMEM);
    cudaFuncSetAttribute(lstm_scan,   cudaFuncAttributeMaxDynamicSharedMemorySize, LS_SMEM);
    cudaFuncSetAttribute(attn_scores, cudaFuncAttributeMaxDynamicSharedMemorySize, SC_SMEM);
    cudaFuncSetAttribute(attn_pv,     cudaFuncAttributeMaxDynamicSharedMemorySize, PV_SMEM);

    embed_kernel<<<2048, 256>>>(x, emb, xe);

    for (int d = 0; d < 2; d++)
        run_gemm(xe, Wih0 + (size_t)d * 2048 * 256, b0 + d * 2048,
                 pre + (size_t)d * 2048 * 2048, 2048, 2048, 256, 2048, 0, xh, xl, wh, wl);
    reset_ctr<<<1, 1>>>(ctr);
    lstm_scan<<<64, 256, LS_SMEM>>>(pre, Whh0, hstate, ha, ctr);

    float* cur = ha;
    float* nxt = hb;
    for (int l = 0; l < 2; l++) {
        for (int d = 0; d < 2; d++)
            run_gemm(cur, Wih12 + (size_t)(l * 2 + d) * 2048 * 1024, b12 + (l * 2 + d) * 2048,
                     pre + (size_t)d * 2048 * 2048, 2048, 2048, 1024, 2048, 0, xh, xl, wh, wl);
        reset_ctr<<<1, 1>>>(ctr);
        lstm_scan<<<64, 256, LS_SMEM>>>(pre, Whh12 + (size_t)l * 2 * 2048 * 512, hstate, nxt, ctr);
        float* t = cur; cur = nxt; nxt = t;
    }

    ln_kernel<<<2048, 256>>>(cur, nullptr, ln_g, ln_b, cur);
    float* H = cur;

    for (int l = 0; l < 6; l++) {
        run_gemm(H, Wqkv + (size_t)l * 3072 * 1024, bqkv + l * 3072,
                 qkv, 2048, 3072, 1024, 3072, 0, xh, xl, wh, wl);
        attn_scores<<<dim3(8, 8, 32), 256, SC_SMEM>>>(qkv, sc);
        attn_softmax<<<2048, 256>>>(sc);
        attn_pv<<<dim3(8, 32), 256, PV_SMEM>>>(sc, qkv, ao);
        run_gemm(ao, Wo + (size_t)l * 1024 * 1024, bo + l * 1024,
                 att, 2048, 1024, 1024, 1024, 0, xh, xl, wh, wl);
        ln_kernel<<<2048, 256>>>(H, att, ln1g + l * 1024, ln1b + l * 1024, H);
        run_gemm(H, W1 + (size_t)l * 4096 * 1024, b1 + l * 4096,
                 ff, 2048, 4096, 1024, 4096, 1, xh, xl, wh, wl);
        run_gemm(ff, W2 + (size_t)l * 1024 * 4096, b2 + l * 1024,
                 att, 2048, 1024, 4096, 1024, 0, xh, xl, wh, wl);
        ln_kernel<<<2048, 256>>>(H, att, ln2g + l * 1024, ln2b + l * 1024, H);
    }

    for (int i = 0; i < 3; i++)
        run_gemm(H, attnW + (size_t)i * 1024 * 1024, attnb + i * 1024,
                 qkv + i * 1024, 2048, 1024, 1024, 3072, 0, xh, xl, wh, wl);
    attn_scores<<<dim3(8, 8, 32), 256, SC_SMEM>>>(qkv, sc);
    attn_softmax<<<2048, 256>>>(sc);
    attn_pv<<<dim3(8, 32), 256, PV_SMEM>>>(sc, qkv, ao);
    run_gemm(ao, attnW + (size_t)3 * 1024 * 1024, attnb + 3 * 1024,
             att, 2048, 1024, 1024, 1024, 0, xh, xl, wh, wl);

    run_gemm(att, outW, outb, OUT, 2048, 32000, 1024, 32000, 0, xh, xl, wh, wl);
}

// round 17
// speedup vs baseline: 1.0128x; 1.0128x over previous
#include <cuda_runtime.h>
#include <cuda_bf16.h>
#include <stdint.h>
#include <math.h>

// Shapes: B=4, S=512, V=32000, E=256, H=512/dir, D=1024, NH=8, dk=128, NLAYERS=6
// M = B*S = 2048 everywhere.

__device__ float         g_xe[2048 * 256];
__device__ float         g_pre[2 * 2048 * 2048];
__device__ float         g_ha[2048 * 1024];
__device__ float         g_hb[2048 * 1024];
__device__ float         g_qkv[2048 * 3072];
__device__ float         g_sc[32 * 512 * 512];
__device__ float         g_ao[2048 * 1024];
__device__ float         g_att[2048 * 1024];
__device__ float         g_ff[2048 * 4096];
__device__ float         g_hstate[2 * 2 * 4 * 512];
__device__ unsigned      g_ctr;
__device__ __nv_bfloat16 g_wh[32000 * 1024];
__device__ __nv_bfloat16 g_wl[32000 * 1024];
__device__ __nv_bfloat16 g_xh[2048 * 4096];
__device__ __nv_bfloat16 g_xl[2048 * 4096];

__device__ __forceinline__ unsigned smem_u32(const void* p) {
    unsigned a;
    asm("{ .reg .u64 t; cvta.to.shared.u64 t, %1; cvt.u32.u64 %0, t; }" : "=r"(a) : "l"(p));
    return a;
}
#define CPA16(sa, g) \
    asm volatile("cp.async.cg.shared.global [%0], [%1], 16;" :: "r"(sa), "l"(g) : "memory")
#define CPA_COMMIT() asm volatile("cp.async.commit_group;" ::: "memory")
#define CPA_WAIT1()  asm volatile("cp.async.wait_group 1;" ::: "memory")

#define LDSM4(r0, r1, r2, r3, addr) \
    asm volatile("ldmatrix.sync.aligned.m8n8.x4.shared.b16 {%0,%1,%2,%3}, [%4];" \
                 : "=r"(r0), "=r"(r1), "=r"(r2), "=r"(r3) : "r"(addr))

#define MMA16(d, a, b0, b1) \
    asm volatile("mma.sync.aligned.m16n8k16.row.col.f32.bf16.bf16.f32 " \
                 "{%0,%1,%2,%3},{%4,%5,%6,%7},{%8,%9},{%0,%1,%2,%3};" \
                 : "+f"((d)[0]), "+f"((d)[1]), "+f"((d)[2]), "+f"((d)[3]) \
                 : "r"((a)[0]), "r"((a)[1]), "r"((a)[2]), "r"((a)[3]), "r"(b0), "r"(b1))

__global__ __launch_bounds__(256) void cvt_split(const float* __restrict__ X,
                                                 __nv_bfloat16* __restrict__ H,
                                                 __nv_bfloat16* __restrict__ L,
                                                 int n4)
{
    const int i = blockIdx.x * 256 + threadIdx.x;
    if (i >= n4) return;
    const float4 v = ((const float4*)X)[i];
    __nv_bfloat16 hx = __float2bfloat16_rn(v.x);
    __nv_bfloat16 hy = __float2bfloat16_rn(v.y);
    __nv_bfloat16 hz = __float2bfloat16_rn(v.z);
    __nv_bfloat16 hw = __float2bfloat16_rn(v.w);
    __nv_bfloat16 lx = __float2bfloat16_rn(v.x - __bfloat162float(hx));
    __nv_bfloat16 ly = __float2bfloat16_rn(v.y - __bfloat162float(hy));
    __nv_bfloat16 lz = __float2bfloat16_rn(v.z - __bfloat162float(hz));
    __nv_bfloat16 lw = __float2bfloat16_rn(v.w - __bfloat162float(hw));
    __nv_bfloat162* H2 = (__nv_bfloat162*)H;
    __nv_bfloat162* L2 = (__nv_bfloat162*)L;
    H2[i * 2]     = __nv_bfloat162(hx, hy);
    H2[i * 2 + 1] = __nv_bfloat162(hz, hw);
    L2[i * 2]     = __nv_bfloat162(lx, ly);
    L2[i * 2 + 1] = __nv_bfloat162(lz, lw);
}

#define TPITCH 144
#define TMAT   (128 * TPITCH)
#define TSTAGE (4 * TMAT)
#define TG_SMEM (2 * TSTAGE)

__device__ __forceinline__ void tg_issue(char* sbase,
                                         const __nv_bfloat16* __restrict__ Ah,
                                         const __nv_bfloat16* __restrict__ Al,
                                         const __nv_bfloat16* __restrict__ Wh,
                                         const __nv_bfloat16* __restrict__ Wl,
                                         int bm, int bn, int K, int k0, int tid)
{
#pragma unroll
    for (int i = 0; i < 16; i++) {
        const int s   = tid + (i << 8);
        const int mat = s >> 10;
        const int r   = (s >> 3) & 127;
        const int cs  = s & 7;
        const __nv_bfloat16* g;
        if (mat == 0)      g = Ah + (size_t)(bm + r) * K + k0 + cs * 8;
        else if (mat == 1) g = Al + (size_t)(bm + r) * K + k0 + cs * 8;
        else if (mat == 2) g = Wh + (size_t)(bn + r) * K + k0 + cs * 8;
        else               g = Wl + (size_t)(bn + r) * K + k0 + cs * 8;
        const unsigned sa = smem_u32(sbase + mat * TMAT + r * TPITCH + cs * 16);
        CPA16(sa, g);
    }
}

__global__ __launch_bounds__(256) void tgemm(const __nv_bfloat16* __restrict__ Ah,
                                             const __nv_bfloat16* __restrict__ Al,
                                             const __nv_bfloat16* __restrict__ Wh,
                                             const __nv_bfloat16* __restrict__ Wl,
                                             const float* __restrict__ bias,
                                             float* __restrict__ C,
                                             int M, int N, int K, int ldc, int relu)
{
    extern __shared__ __align__(128) char sm[];
    const int tid  = threadIdx.x;
    const int wid  = tid >> 5;
    const int lane = tid & 31;
    const int wm   = wid >> 2;
    const int wn   = wid & 3;
    const int bm   = blockIdx.y << 7;
    const int bn   = blockIdx.x << 7;
    const int nch  = K >> 6;

    tg_issue(sm,          Ah, Al, Wh, Wl, bm, bn, K, 0,  tid);
    CPA_COMMIT();
    tg_issue(sm + TSTAGE, Ah, Al, Wh, Wl, bm, bn, K, 64, tid);
    CPA_COMMIT();

    float acc[4][4][4];
#pragma unroll
    for (int a = 0; a < 4; a++)
#pragma unroll
        for (int b = 0; b < 4; b++)
#pragma unroll
            for (int c = 0; c < 4; c++) acc[a][b][c] = 0.f;

    for (int c = 0; c < nch; c++) {
        CPA_WAIT1();
        __syncthreads();
        char* sb = sm + (c & 1) * TSTAGE;
        const unsigned sA = smem_u32(sb);

#pragma unroll
        for (int k16 = 0; k16 < 4; k16++) {
            const unsigned kb   = (unsigned)(k16 * 32 + ((lane >> 4) << 4));
            const unsigned arow = (unsigned)(lane & 15);

            unsigned ah[4][4], al[4][4];
#pragma unroll
            for (int mt = 0; mt < 4; mt++) {
                const unsigned ra = sA + (wm * 64 + mt * 16 + arow) * TPITCH + kb;
                LDSM4(ah[mt][0], ah[mt][1], ah[mt][2], ah[mt][3], ra);
                LDSM4(al[mt][0], al[mt][1], al[mt][2], al[mt][3], ra + TMAT);
            }
#pragma unroll
            for (int np = 0; np < 2; np++) {
                const unsigned rb = sA + 2 * TMAT + (wn * 32 + np * 16 + arow) * TPITCH + kb;
                unsigned bh[4], bl[4];
                LDSM4(bh[0], bh[1], bh[2], bh[3], rb);
                LDSM4(bl[0], bl[1], bl[2], bl[3], rb + TMAT);
#pragma unroll
                for (int mt = 0; mt < 4; mt++) {
                    MMA16(acc[mt][np * 2],     ah[mt], bh[0], bh[2]);
                    MMA16(acc[mt][np * 2],     ah[mt], bl[0], bl[2]);
                    MMA16(acc[mt][np * 2],     al[mt], bh[0], bh[2]);
                    MMA16(acc[mt][np * 2 + 1], ah[mt], bh[1], bh[3]);
                    MMA16(acc[mt][np * 2 + 1], ah[mt], bl[1], bl[3]);
                    MMA16(acc[mt][np * 2 + 1], al[mt], bh[1], bh[3]);
                }
            }
        }
        __syncthreads();
        if (c + 2 < nch)
            tg_issue(sm + (c & 1) * TSTAGE, Ah, Al, Wh, Wl, bm, bn, K, (c + 2) * 64, tid);
        CPA_COMMIT();
    }

#pragma unroll
    for (int mt = 0; mt < 4; mt++) {
#pragma unroll
        for (int nt = 0; nt < 4; nt++) {
            const int r0 = bm + wm * 64 + mt * 16 + (lane >> 2);
            const int cl = bn + wn * 32 + nt * 8 + (lane & 3) * 2;
            const float b0v = bias[cl], b1v = bias[cl + 1];
            float v0 = acc[mt][nt][0] + b0v;
            float v1 = acc[mt][nt][1] + b1v;
            float v2 = acc[mt][nt][2] + b0v;
            float v3 = acc[mt][nt][3] + b1v;
            if (relu) {
                v0 = fmaxf(v0, 0.f); v1 = fmaxf(v1, 0.f);
                v2 = fmaxf(v2, 0.f); v3 = fmaxf(v3, 0.f);
            }
            C[(size_t)r0 * ldc + cl]           = v0;
            C[(size_t)r0 * ldc + cl + 1]       = v1;
            C[(size_t)(r0 + 8) * ldc + cl]     = v2;
            C[(size_t)(r0 + 8) * ldc + cl + 1] = v3;
        }
    }
}

__global__ void embed_kernel(const int* __restrict__ x,
                             const float* __restrict__ emb,
                             float* __restrict__ out)
{
    const int row = blockIdx.x;
    const int tid = threadIdx.x;
    const int idx = x[row];
    out[(size_t)row * 256 + tid] = emb[(size_t)idx * 256 + tid];
}

#define LS_WP 516
#define LS_SMEM ((64 * LS_WP + 4 * LS_WP + 256 + 64) * 4)

__global__ __launch_bounds__(256) void lstm_scan(const float* __restrict__ pre,
                                                 const float* __restrict__ Whh,
                                                 float* __restrict__ hstate,
                                                 float* __restrict__ out,
                                                 unsigned* __restrict__ ctr)
{
    extern __shared__ float ls_sm[];
    float* wsm = ls_sm;
    float* hsm = ls_sm + 64 * LS_WP;
    float* gsm = hsm + 4 * LS_WP;
    float* csm = gsm + 256;

    const int tid  = threadIdx.x;
    const int dir  = blockIdx.x >> 5;
    const int base = (blockIdx.x & 31) << 4;
    const int gu   = tid >> 2;
    const int b    = tid & 3;
    const int grow = ((gu >> 4) << 9) + base + (gu & 15);

    const float* Wd   = Whh + (size_t)dir * 2048 * 512;
    const float* pred = pre + (size_t)dir * 2048 * 2048;

    for (int i = tid; i < 64 * 128; i += 256) {
        const int row = i >> 7;
        const int c   = (i & 127) << 2;
        const float4 v = *(const float4*)&Wd[(size_t)(((row >> 4) << 9) + base + (row & 15)) * 512 + c];
        float* w = &wsm[row * LS_WP + c];
        w[0] = v.x; w[1] = v.y; w[2] = v.z; w[3] = v.w;
    }
    if (tid < 64) {
        csm[tid] = 0.f;
        const int uu = tid >> 2, bb = tid & 3;
        hstate[((dir * 2 + 0) * 4 + bb) * 512 + base + uu] = 0.f;
    }
    __threadfence();
    __syncthreads();

    unsigned want = gridDim.x;
    if (tid == 0) {
        atomicAdd(ctr, 1u);
        while (*(volatile unsigned*)ctr < want) __nanosleep(64);
        __threadfence();
    }
    __syncthreads();

    for (int t = 0; t < 512; t++) {
        const int s  = dir ? (511 - t) : t;
        const int rb = t & 1;

        const float* hg = hstate + (size_t)(dir * 2 + rb) * 4 * 512;
        for (int i = tid; i < 2048; i += 256)
            hsm[(i >> 9) * LS_WP + (i & 511)] = hg[i];
        __syncthreads();

        float acc = pred[(size_t)((b << 9) + s) * 2048 + grow];
        const float* wr = wsm + gu * LS_WP;
        const float* hr = hsm + b * LS_WP;
#pragma unroll 8
        for (int k = 0; k < 512; k += 4) {
            const float4 w = *(const float4*)(wr + k);
            const float4 h = *(const float4*)(hr + k);
            acc += w.x * h.x + w.y * h.y + w.z * h.z + w.w * h.w;
        }
        gsm[tid] = acc;
        __syncthreads();

        if (tid < 64) {
            const int uu = tid >> 2, bb = tid & 3;
            const float iv = 1.f / (1.f + expf(-gsm[tid]));
            const float fv = 1.f / (1.f + expf(-gsm[64 + tid]));
            const float gv = tanhf(gsm[128 + tid]);
            const float ov = 1.f / (1.f + expf(-gsm[192 + tid]));
            const float c  = fv * csm[tid] + iv * gv;
            csm[tid] = c;
            const float h = ov * tanhf(c);
            hstate[((dir * 2 + (rb ^ 1)) * 4 + bb) * 512 + base + uu] = h;
            out[(size_t)((bb << 9) + s) * 1024 + (dir << 9) + base + uu] = h;
            __threadfence();
        }
        __syncthreads();

        want += gridDim.x;
        if (tid == 0) {
            atomicAdd(ctr, 1u);
            while (*(volatile unsigned*)ctr < want) __nanosleep(64);
            __threadfence();
        }
        __syncthreads();
    }
}

__global__ void reset_ctr(unsigned* c) { *c = 0u; }

__global__ __launch_bounds__(256) void ln_kernel(const float* __restrict__ X,
                                                 const float* __restrict__ R,
                                                 const float* __restrict__ g,
                                                 const float* __restrict__ bta,
                                                 float* __restrict__ Y)
{
    __shared__ float red[16];
    const int row = blockIdx.x;
    const int tid = threadIdx.x;
    const size_t off = (size_t)row * 1024;

    float loc[4];
    float s = 0.f;
#pragma unroll
    for (int i = 0; i < 4; i++) {
        const int c = tid + i * 256;
        float v = X[off + c];
        if (R) v += R[off + c];
        loc[i] = v;
        s += v;
    }
#pragma unroll
    for (int o = 16; o; o >>= 1) s += __shfl_xor_sync(0xffffffffu, s, o);
    if ((tid & 31) == 0) red[tid >> 5] = s;
    __syncthreads();
    if (tid == 0) { float t = 0; for (int i = 0; i < 8; i++) t += red[i]; red[8] = t; }
    __syncthreads();
    const float mean = red[8] * (1.f / 1024.f);

    float s2 = 0.f;
#pragma unroll
    for (int i = 0; i < 4; i++) { const float d = loc[i] - mean; s2 += d * d; }
#pragma unroll
    for (int o = 16; o; o >>= 1) s2 += __shfl_xor_sync(0xffffffffu, s2, o);
    __syncthreads();
    if ((tid & 31) == 0) red[tid >> 5] = s2;
    __syncthreads();
    if (tid == 0) { float t = 0; for (int i = 0; i < 8; i++) t += red[i]; red[8] = t; }
    __syncthreads();
    const float inv = rsqrtf(red[8] * (1.f / 1024.f) + 1e-5f);

#pragma unroll
    for (int i = 0; i < 4; i++) {
        const int c = tid + i * 256;
        Y[off + c] = (loc[i] - mean) * inv * g[c] + bta[c];
    }
}

#define SC_SMEM (2 * 64 * 129 * 4)
__global__ __launch_bounds__(256) void attn_scores(const float* __restrict__ qkv,
                                                   float* __restrict__ sc)
{
    extern __shared__ float smq[];
    float* Qs = smq;
    float* Ks = smq + 64 * 129;

    const int bh = blockIdx.z;
    const int b  = bh >> 3, h = bh & 7;
    const int q0 = blockIdx.y << 6, k0 = blockIdx.x << 6;
    const int tid = threadIdx.x;

    const float* Qg = qkv + (size_t)(b * 512 + q0) * 3072 + h * 128;
    const float* Kg = qkv + (size_t)(b * 512 + k0) * 3072 + 1024 + h * 128;

    for (int i = tid; i < 64 * 128; i += 256) {
        const int r = i >> 7, c = i & 127;
        Qs[r * 129 + c] = Qg[(size_t)r * 3072 + c];
        Ks[r * 129 + c] = Kg[(size_t)r * 3072 + c];
    }
    __syncthreads();

    const int tx = tid & 15, ty = tid >> 4;
    float acc[4][4];
#pragma unroll
    for (int i = 0; i < 4; i++)
#pragma unroll
        for (int j = 0; j < 4; j++) acc[i][j] = 0.f;

    for (int kk = 0; kk < 128; kk++) {
        float ar[4], br[4];
#pragma unroll
        for (int i = 0; i < 4; i++) ar[i] = Qs[(ty * 4 + i) * 129 + kk];
#pragma unroll
        for (int j = 0; j < 4; j++) br[j] = Ks[(tx * 4 + j) * 129 + kk];
#pragma unroll
        for (int i = 0; i < 4; i++)
#pragma unroll
            for (int j = 0; j < 4; j++) acc[i][j] += ar[i] * br[j];
    }

    const float scale = 0.08838834764831845f;
    float* o = sc + ((size_t)bh * 512 + q0) * 512 + k0;
#pragma unroll
    for (int i = 0; i < 4; i++)
#pragma unroll
        for (int j = 0; j < 4; j++)
            o[(size_t)(ty * 4 + i) * 512 + tx * 4 + j] = acc[i][j] * scale;
}

__global__ __launch_bounds__(256) void attn_softmax(float* __restrict__ sc)
{
    const int row  = blockIdx.x * 8 + (threadIdx.x >> 5);
    const int lane = threadIdx.x & 31;
    float* p = sc + (size_t)row * 512;

    float v[16];
    float m = -1e30f;
#pragma unroll
    for (int i = 0; i < 16; i++) { v[i] = p[lane + i * 32]; m = fmaxf(m, v[i]); }
#pragma unroll
    for (int o = 16; o; o >>= 1) m = fmaxf(m, __shfl_xor_sync(0xffffffffu, m, o));
    float s = 0.f;
#pragma unroll
    for (int i = 0; i < 16; i++) { v[i] = expf(v[i] - m); s += v[i]; }
#pragma unroll
    for (int o = 16; o; o >>= 1) s += __shfl_xor_sync(0xffffffffu, s, o);
    const float r = 1.f / s;
#pragma unroll
    for (int i = 0; i < 16; i++) p[lane + i * 32] = v[i] * r;
}

#define PV_SMEM ((64 * 65 + 64 * 129) * 4)
__global__ __launch_bounds__(256) void attn_pv(const float* __restrict__ sc,
                                               const float* __restrict__ qkv,
                                               float* __restrict__ ao)
{
    extern __shared__ float smp[];
    float* Ws = smp;
    float* Vs = smp + 64 * 65;

    const int bh = blockIdx.y;
    const int b  = bh >> 3, h = bh & 7;
    const int q0 = blockIdx.x << 6;
    const int tid = threadIdx.x;
    const int tx = tid & 15, ty = tid >> 4;

    const float* scb = sc + ((size_t)bh * 512 + q0) * 512;
    const float* Vg  = qkv + (size_t)b * 512 * 3072 + 2048 + h * 128;

    float acc[4][8];
#pragma unroll
    for (int i = 0; i < 4; i++)
#pragma unroll
        for (int j = 0; j < 8; j++) acc[i][j] = 0.f;

    for (int kt = 0; kt < 512; kt += 64) {
        for (int i = tid; i < 64 * 64; i += 256) {
            const int r = i >> 6, c = i & 63;
            Ws[r * 65 + c] = scb[(size_t)r * 512 + kt + c];
        }
        for (int i = tid; i < 64 * 128; i += 256) {
            const int r = i >> 7, c = i & 127;
            Vs[r * 129 + c] = Vg[(size_t)(kt + r) * 3072 + c];
        }
        __syncthreads();
        for (int kk = 0; kk < 64; kk++) {
            float ar[4], br[8];
#pragma unroll
            for (int i = 0; i < 4; i++) ar[i] = Ws[(ty * 4 + i) * 65 + kk];
#pragma unroll
            for (int j = 0; j < 8; j++) br[j] = Vs[kk * 129 + tx * 8 + j];
#pragma unroll
            for (int i = 0; i < 4; i++)
#pragma unroll
                for (int j = 0; j < 8; j++) acc[i][j] += ar[i] * br[j];
        }
        __syncthreads();
    }

    float* og = ao + (size_t)(b * 512 + q0) * 1024 + h * 128;
#pragma unroll
    for (int i = 0; i < 4; i++)
#pragma unroll
        for (int j = 0; j < 8; j++)
            og[(size_t)(ty * 4 + i) * 1024 + tx * 8 + j] = acc[i][j];
}

static void run_gemm(const float* A, const float* W, const float* bias, float* C,
                     int M, int N, int K, int ldc, int relu,
                     __nv_bfloat16* xh, __nv_bfloat16* xl,
                     __nv_bfloat16* wh, __nv_bfloat16* wl)
{
    const int na4 = (M * K) / 4;
    const int nw4 = (N * K) / 4;
    cvt_split<<<(na4 + 255) / 256, 256>>>(A, xh, xl, na4);
    cvt_split<<<(nw4 + 255) / 256, 256>>>(W, wh, wl, nw4);
    tgemm<<<dim3(N / 128, M / 128), 256, TG_SMEM>>>(xh, xl, wh, wl, bias, C, M, N, K, ldc, relu);
}

extern "C" void kernel_launch(void* const* d_in, const int* in_sizes, int n_in,
                              void* d_out, int out_size)
{
    (void)in_sizes; (void)n_in; (void)out_size;

    const int*   x     = (const int*)  d_in[0];
    const float* emb   = (const float*)d_in[1];
    const float* Wih0  = (const float*)d_in[2];
    const float* Whh0  = (const float*)d_in[3];
    const float* b0    = (const float*)d_in[4];
    const float* Wih12 = (const float*)d_in[5];
    const float* Whh12 = (const float*)d_in[6];
    const float* b12   = (const float*)d_in[7];
    const float* ln_g  = (const float*)d_in[8];
    const float* ln_b  = (const float*)d_in[9];
    const float* Wqkv  = (const float*)d_in[10];
    const float* bqkv  = (const float*)d_in[11];
    const float* Wo    = (const float*)d_in[12];
    const float* bo    = (const float*)d_in[13];
    const float* ln1g  = (const float*)d_in[14];
    const float* ln1b  = (const float*)d_in[15];
    const float* W1    = (const float*)d_in[16];
    const float* b1    = (const float*)d_in[17];
    const float* W2    = (const float*)d_in[18];
    const float* b2    = (const float*)d_in[19];
    const float* ln2g  = (const float*)d_in[20];
    const float* ln2b  = (const float*)d_in[21];
    const float* attnW = (const float*)d_in[22];
    const float* attnb = (const float*)d_in[23];
    const float* outW  = (const float*)d_in[24];
    const float* outb  = (const float*)d_in[25];
    float* OUT = (float*)d_out;

    float *xe, *pre, *ha, *hb, *qkv, *sc, *ao, *att, *ff, *hstate;
    unsigned* ctr;
    __nv_bfloat16 *wh, *wl, *xh, *xl;
    cudaGetSymbolAddress((void**)&xe, g_xe);
    cudaGetSymbolAddress((void**)&pre, g_pre);
    cudaGetSymbolAddress((void**)&ha, g_ha);
    cudaGetSymbolAddress((void**)&hb, g_hb);
    cudaGetSymbolAddress((void**)&qkv, g_qkv);
    cudaGetSymbolAddress((void**)&sc, g_sc);
    cudaGetSymbolAddress((void**)&ao, g_ao);
    cudaGetSymbolAddress((void**)&att, g_att);
    cudaGetSymbolAddress((void**)&ff, g_ff);
    cudaGetSymbolAddress((void**)&hstate, g_hstate);
    cudaGetSymbolAddress((void**)&ctr, g_ctr);
    cudaGetSymbolAddress((void**)&wh, g_wh);
    cudaGetSymbolAddress((void**)&wl, g_wl);
    cudaGetSymbolAddress((void**)&xh, g_xh);
    cudaGetSymbolAddress((void**)&xl, g_xl);

    cudaFuncSetAttribute(tgemm,       cudaFuncAttributeMaxDynamicSharedMemorySize, TG_SMEM);
    cudaFuncSetAttribute(lstm_scan,   cudaFuncAttributeMaxDynamicSharedMemorySize, LS_SMEM);
    cudaFuncSetAttribute(attn_scores, cudaFuncAttributeMaxDynamicSharedMemorySize, SC_SMEM);
    cudaFuncSetAttribute(attn_pv,     cudaFuncAttributeMaxDynamicSharedMemorySize, PV_SMEM);

    embed_kernel<<<2048, 256>>>(x, emb, xe);

    for (int d = 0; d < 2; d++)
        run_gemm(xe, Wih0 + (size_t)d * 2048 * 256, b0 + d * 2048,
                 pre + (size_t)d * 2048 * 2048, 2048, 2048, 256, 2048, 0, xh, xl, wh, wl);
    reset_ctr<<<1, 1>>>(ctr);
    lstm_scan<<<64, 256, LS_SMEM>>>(pre, Whh0, hstate, ha, ctr);

    float* cur = ha;
    float* nxt = hb;
    for (int l = 0; l < 2; l++) {
        for (int d = 0; d < 2; d++)
            run_gemm(cur, Wih12 + (size_t)(l * 2 + d) * 2048 * 1024, b12 + (l * 2 + d) * 2048,
                     pre + (size_t)d * 2048 * 2048, 2048, 2048, 1024, 2048, 0, xh, xl, wh, wl);
        reset_ctr<<<1, 1>>>(ctr);
        lstm_scan<<<64, 256, LS_SMEM>>>(pre, Whh12 + (size_t)l * 2 * 2048 * 512, hstate, nxt, ctr);
        float* t = cur; cur = nxt; nxt = t;
    }

    ln_kernel<<<2048, 256>>>(cur, nullptr, ln_g, ln_b, cur);
    float* H = cur;

    for (int l = 0; l < 6; l++) {
        run_gemm(H, Wqkv + (size_t)l * 3072 * 1024, bqkv + l * 3072,
                 qkv, 2048, 3072, 1024, 3072, 0, xh, xl, wh, wl);
        attn_scores<<<dim3(8, 8, 32), 256, SC_SMEM>>>(qkv, sc);
        attn_softmax<<<2048, 256>>>(sc);
        attn_pv<<<dim3(8, 32), 256, PV_SMEM>>>(sc, qkv, ao);
        run_gemm(ao, Wo + (size_t)l * 1024 * 1024, bo + l * 1024,
                 att, 2048, 1024, 1024, 1024, 0, xh, xl, wh, wl);
        ln_kernel<<<2048, 256>>>(H, att, ln1g + l * 1024, ln1b + l * 1024, H);
        run_gemm(H, W1 + (size_t)l * 4096 * 1024, b1 + l * 4096,
                 ff, 2048, 4096, 1024, 4096, 1, xh, xl, wh, wl);
        run_gemm(ff, W2 + (size_t)l * 1024 * 4096, b2 + l * 1024,
                 att, 2048, 1024, 4096, 1024, 0, xh, xl, wh, wl);
        ln_kernel<<<2048, 256>>>(H, att, ln2g + l * 1024, ln2b + l * 1024, H);
    }

    for (int i = 0; i < 3; i++)
        run_gemm(H, attnW + (size_t)i * 1024 * 1024, attnb + i * 1024,
                 qkv + i * 1024, 2048, 1024, 1024, 3072, 0, xh, xl, wh, wl);
    attn_scores<<<dim3(8, 8, 32), 256, SC_SMEM>>>(qkv, sc);
    attn_softmax<<<2048, 256>>>(sc);
    attn_pv<<<dim3(8, 32), 256, PV_SMEM>>>(sc, qkv, ao);
    run_gemm(ao, attnW + (size_t)3 * 1024 * 1024, attnb + 3 * 1024,
             att, 2048, 1024, 1024, 1024, 0, xh, xl, wh, wl);

    run_gemm(att, outW, outb, OUT, 2048, 32000, 1024, 32000, 0, xh, xl, wh, wl);
}